// round 3
// baseline (speedup 1.0000x reference)
#include <cuda_runtime.h>
#include <math.h>

#define B_TOT  8192
#define SEQ    100
#define INF    15
#define HID    128
#define FUT    30
#define ROWS   32
#define RP     36                 // padded row stride (floats); 36/4=9 odd -> conflict-free LDS.128
#define NCTA   (B_TOT / ROWS)     // 256
#define NTHR   256

typedef unsigned long long ull;

// ---- transposed, gate-interleaved weights: [k][j][4 gates] as float4 ----
// segments (float4 units): X:0(+1920)  H0:1920(+16384)  I1:18304(+16384)  H1:34688(+16384)
#define OFF_X   0
#define OFF_H0  1920
#define OFF_I1  18304
#define OFF_H1  34688
#define WT_TOT4 51072
__device__ float4 g_wt4[WT_TOT4];

__global__ void transpose_weights(const float* __restrict__ w_ih0,
                                  const float* __restrict__ w_hh0,
                                  const float* __restrict__ w_ih1,
                                  const float* __restrict__ w_hh1) {
    int idx = blockIdx.x * blockDim.x + threadIdx.x;
    if (idx >= WT_TOT4) return;
    const float* W; int K; int local;
    if      (idx < OFF_H0) { W = w_ih0; K = INF; local = idx; }
    else if (idx < OFF_I1) { W = w_hh0; K = HID; local = idx - OFF_H0; }
    else if (idx < OFF_H1) { W = w_ih1; K = HID; local = idx - OFF_I1; }
    else                   { W = w_hh1; K = HID; local = idx - OFF_H1; }
    int k = local >> 7;
    int j = local & 127;
    float4 v;
    v.x = W[(0 * HID + j) * K + k];   // gate i
    v.y = W[(1 * HID + j) * K + k];   // gate f
    v.z = W[(2 * HID + j) * K + k];   // gate g
    v.w = W[(3 * HID + j) * K + k];   // gate o
    g_wt4[idx] = v;
}

// ---- packed f32x2 helpers ----
__device__ __forceinline__ ull pk2(float x, float y) {
    ull r; asm("mov.b64 %0,{%1,%2};" : "=l"(r) : "f"(x), "f"(y)); return r;
}
__device__ __forceinline__ void fma2(ull& d, ull a, ull b) {
    asm("fma.rn.f32x2 %0, %1, %2, %0;" : "+l"(d) : "l"(a), "l"(b));
}
__device__ __forceinline__ float2 up2(ull v) {
    float2 r; asm("mov.b64 {%0,%1},%2;" : "=f"(r.x), "=f"(r.y) : "l"(v)); return r;
}

__device__ __forceinline__ float sigf(float x) {
    return __fdividef(1.0f, 1.0f + __expf(-x));
}
__device__ __forceinline__ float tanhfast(float x) {
    return 1.0f - __fdividef(2.0f, __expf(2.0f * x) + 1.0f);
}

struct Smem {
    float h0t[HID][RP];
    float c0t[HID][RP];
    float h1t[HID][RP];
    float c1t[HID][RP];
    float xt[16][RP];      // layer-0 input, k-major (row 15 unused)
    float fcw[2][HID];
};

// acc[p][g] (+=) packed row-pair p (rows r0+2p, r0+2p+1) for gate g.
// At: k-major activations with row stride RP. Wt: gate-interleaved float4 per (k,j).
template <int K>
__device__ __forceinline__ void mm_acc(ull acc[8][4],
                                       const float* __restrict__ At,
                                       const float4* __restrict__ Wt,
                                       int j, int r0) {
#pragma unroll 4
    for (int k = 0; k < K; ++k) {
        float4 w = __ldg(&Wt[k * HID + j]);
        ull w0 = pk2(w.x, w.x);
        ull w1 = pk2(w.y, w.y);
        ull w2 = pk2(w.z, w.z);
        ull w3 = pk2(w.w, w.w);
        const float* a = At + k * RP + r0;
        ulonglong2 q0 = *reinterpret_cast<const ulonglong2*>(a);
        ulonglong2 q1 = *reinterpret_cast<const ulonglong2*>(a + 4);
        ulonglong2 q2 = *reinterpret_cast<const ulonglong2*>(a + 8);
        ulonglong2 q3 = *reinterpret_cast<const ulonglong2*>(a + 12);
        ull av[8] = {q0.x, q0.y, q1.x, q1.y, q2.x, q2.y, q3.x, q3.y};
#pragma unroll
        for (int p = 0; p < 8; ++p) {
            fma2(acc[p][0], av[p], w0);
            fma2(acc[p][1], av[p], w1);
            fma2(acc[p][2], av[p], w2);
            fma2(acc[p][3], av[p], w3);
        }
    }
}

// LSTM gate epilogue: consumes acc, updates c (SMEM, thread-private column) and h.
__device__ __forceinline__ void epilogue(ull acc[8][4], float* hb, float* cb) {
#pragma unroll
    for (int p = 0; p < 8; ++p) {
        float2 gi = up2(acc[p][0]);
        float2 gf = up2(acc[p][1]);
        float2 gg = up2(acc[p][2]);
        float2 go = up2(acc[p][3]);
        float cA = sigf(gf.x) * cb[2 * p]     + sigf(gi.x) * tanhfast(gg.x);
        float cB = sigf(gf.y) * cb[2 * p + 1] + sigf(gi.y) * tanhfast(gg.y);
        cb[2 * p]     = cA;
        cb[2 * p + 1] = cB;
        hb[2 * p]     = sigf(go.x) * tanhfast(cA);
        hb[2 * p + 1] = sigf(go.y) * tanhfast(cB);
    }
}

__global__ void __launch_bounds__(NTHR, 2)
lstm_traj_kernel(const float* __restrict__ x,
                 const float* __restrict__ b_ih0, const float* __restrict__ b_hh0,
                 const float* __restrict__ b_ih1, const float* __restrict__ b_hh1,
                 const float* __restrict__ fc_w, const float* __restrict__ fc_b,
                 float* __restrict__ out) {
    extern __shared__ char smraw[];
    Smem& sm = *reinterpret_cast<Smem*>(smraw);

    const int tid   = threadIdx.x;
    const int j     = tid & (HID - 1);     // hidden unit owned by this thread
    const int r0    = (tid >> 7) * 16;     // first of 16 batch rows this thread owns
    const int brow0 = blockIdx.x * ROWS;

    const float4* WX  = g_wt4 + OFF_X;
    const float4* WH0 = g_wt4 + OFF_H0;
    const float4* WI1 = g_wt4 + OFF_I1;
    const float4* WH1 = g_wt4 + OFF_H1;

    // zero states, stage fc_w
    for (int i = tid; i < HID * RP; i += NTHR) {
        (&sm.h0t[0][0])[i] = 0.0f;
        (&sm.c0t[0][0])[i] = 0.0f;
        (&sm.h1t[0][0])[i] = 0.0f;
        (&sm.c1t[0][0])[i] = 0.0f;
    }
    if (tid < 2 * HID) (&sm.fcw[0][0])[tid] = fc_w[tid];

    // combined biases (gate order i, f, g, o)
    const float bi0 = b_ih0[j]           + b_hh0[j];
    const float bf0 = b_ih0[HID + j]     + b_hh0[HID + j];
    const float bg0 = b_ih0[2 * HID + j] + b_hh0[2 * HID + j];
    const float bo0 = b_ih0[3 * HID + j] + b_hh0[3 * HID + j];
    const float bi1 = b_ih1[j]           + b_hh1[j];
    const float bf1 = b_ih1[HID + j]     + b_hh1[HID + j];
    const float bg1 = b_ih1[2 * HID + j] + b_hh1[2 * HID + j];
    const float bo1 = b_ih1[3 * HID + j] + b_hh1[3 * HID + j];

    float* hb0 = &sm.h0t[j][r0];
    float* cb0 = &sm.c0t[j][r0];
    float* hb1 = &sm.h1t[j][r0];
    float* cb1 = &sm.c1t[j][r0];

    ull acc[8][4];

    for (int t = 0; t < SEQ + FUT; ++t) {
        const bool enc = (t < SEQ);

        if (enc) {
            // stage x_t transposed: xt[c][r]
            for (int i = tid; i < ROWS * INF; i += NTHR) {
                int r = i / INF;
                int c = i - r * INF;
                sm.xt[c][r] = x[(size_t)(brow0 + r) * (SEQ * INF) + (size_t)t * INF + c];
            }
        }
        __syncthreads();   // (A) xt visible (enc stage or decoder feedback)

        // ---- layer 0: gates = x @ Wih0^T + h0 @ Whh0^T + b0 ----
        {
            ull b0q = pk2(bi0, bi0), b1q = pk2(bf0, bf0);
            ull b2q = pk2(bg0, bg0), b3q = pk2(bo0, bo0);
#pragma unroll
            for (int p = 0; p < 8; ++p) {
                acc[p][0] = b0q; acc[p][1] = b1q; acc[p][2] = b2q; acc[p][3] = b3q;
            }
        }
        mm_acc<INF>(acc, &sm.xt[0][0],  WX,  j, r0);
        mm_acc<HID>(acc, &sm.h0t[0][0], WH0, j, r0);
        __syncthreads();   // (B) all reads of old h0t done
        epilogue(acc, hb0, cb0);
        __syncthreads();   // (C) new h0t visible

        // ---- layer 1: gates = h0 @ Wih1^T + h1 @ Whh1^T + b1 ----
        {
            ull b0q = pk2(bi1, bi1), b1q = pk2(bf1, bf1);
            ull b2q = pk2(bg1, bg1), b3q = pk2(bo1, bo1);
#pragma unroll
            for (int p = 0; p < 8; ++p) {
                acc[p][0] = b0q; acc[p][1] = b1q; acc[p][2] = b2q; acc[p][3] = b3q;
            }
        }
        mm_acc<HID>(acc, &sm.h0t[0][0], WI1, j, r0);
        mm_acc<HID>(acc, &sm.h1t[0][0], WH1, j, r0);
        __syncthreads();   // (D) all reads of old h1t done
        epilogue(acc, hb1, cb1);

        // ---- decoder head: pred = h1 @ fc_w^T + fc_b; feed back into xt[0:2] ----
        if (!enc) {
            __syncthreads();   // (E) new h1t visible
            if (tid < 64) {
                int r = tid >> 1;
                int o = tid & 1;
                float s = __ldg(&fc_b[o]);
                const float* fw = &sm.fcw[o][0];
#pragma unroll 8
                for (int jj = 0; jj < HID; ++jj)
                    s += sm.h1t[jj][r] * fw[jj];
                out[(size_t)(brow0 + r) * (FUT * 2) + (size_t)(t - SEQ) * 2 + o] = s;
                sm.xt[o][r] = s;   // autoregressive feedback into features 0:2
            }
            // next iteration's sync (A) publishes xt to all threads
        }
    }
}

extern "C" void kernel_launch(void* const* d_in, const int* in_sizes, int n_in,
                              void* d_out, int out_size) {
    const float* x     = (const float*)d_in[0];
    const float* w_ih0 = (const float*)d_in[1];
    const float* w_hh0 = (const float*)d_in[2];
    const float* b_ih0 = (const float*)d_in[3];
    const float* b_hh0 = (const float*)d_in[4];
    const float* w_ih1 = (const float*)d_in[5];
    const float* w_hh1 = (const float*)d_in[6];
    const float* b_ih1 = (const float*)d_in[7];
    const float* b_hh1 = (const float*)d_in[8];
    const float* fc_w  = (const float*)d_in[9];
    const float* fc_b  = (const float*)d_in[10];
    float* out = (float*)d_out;

    transpose_weights<<<(WT_TOT4 + 255) / 256, 256>>>(w_ih0, w_hh0, w_ih1, w_hh1);

    cudaFuncSetAttribute(lstm_traj_kernel,
                         cudaFuncAttributeMaxDynamicSharedMemorySize,
                         (int)sizeof(Smem));
    lstm_traj_kernel<<<NCTA, NTHR, sizeof(Smem)>>>(
        x, b_ih0, b_hh0, b_ih1, b_hh1, fc_w, fc_b, out);
}

// round 5
// speedup vs baseline: 2.7704x; 2.7704x over previous
#include <cuda_runtime.h>
#include <cuda_bf16.h>
#include <math.h>

#define B_TOT  8192
#define SEQ    100
#define INF    15
#define HID    128
#define FUT    30
#define MROWS  64
#define NCTA   (B_TOT / MROWS)   // 128
#define NTHR   512
#define PH     136               // h-plane pitch (bf16 elems); 272B rows -> conflict-free ldmatrix
#define PHB    272
#define PX     24                // x-plane pitch
#define PXB    48
#define CP     132               // c-plane pitch (fp32)

// ---- weight fragment buffer: B-frag-layout packed, hi/lo bf16 ----
// chunk = 16 k's; per chunk: 64 n8-tiles x 32 lanes x uint4 {hi_r0, hi_r1, lo_r0, lo_r1}
#define CHK    2048              // uint4 per chunk
#define WB_X   0                 // 1 chunk  (x projection, K=15 padded to 16)
#define WB_H0  (1  * CHK)        // 8 chunks (w_hh0)
#define WB_I1  (9  * CHK)        // 8 chunks (w_ih1)
#define WB_H1  (17 * CHK)        // 8 chunks (w_hh1)
#define WB_TOT (25 * CHK)
__device__ uint4 g_wb[WB_TOT];

__device__ __forceinline__ unsigned short bf16bits(float v) {
    __nv_bfloat16 b = __float2bfloat16(v);
    return reinterpret_cast<unsigned short&>(b);
}

// One thread per (chunk, ntile, lane): pack 8 source fp32 -> uint4 of bf16 frags.
// B frag (m16n8k16 col): reg r, half h -> element [k = r*8 + (lane%4)*2 + h][n = lane/4]
// n' (gate-interleaved) = ntile*8 + lane/4 ; j = n'>>2, g = n'&3 ; src row = g*128 + j
__global__ void pack_weights(const float* __restrict__ w_ih0,
                             const float* __restrict__ w_hh0,
                             const float* __restrict__ w_ih1,
                             const float* __restrict__ w_hh1) {
    int idx = blockIdx.x * blockDim.x + threadIdx.x;
    if (idx >= WB_TOT) return;
    int lane  = idx & 31;
    int ntile = (idx >> 5) & 63;
    int cg    = idx >> 11;          // 0..24
    const float* W; int Ksrc; int lc;
    if      (cg == 0)  { W = w_ih0; Ksrc = INF; lc = 0; }
    else if (cg <= 8)  { W = w_hh0; Ksrc = HID; lc = cg - 1; }
    else if (cg <= 16) { W = w_ih1; Ksrc = HID; lc = cg - 9; }
    else               { W = w_hh1; Ksrc = HID; lc = cg - 17; }

    int np = ntile * 8 + (lane >> 2);
    int j  = np >> 2;
    int g  = np & 3;
    int row = g * HID + j;

    unsigned int u[4];
    for (int r = 0; r < 2; ++r) {
        unsigned short hi[2], lo[2];
        for (int h = 0; h < 2; ++h) {
            int k = lc * 16 + r * 8 + (lane & 3) * 2 + h;
            float v = (k < Ksrc) ? W[(size_t)row * Ksrc + k] : 0.0f;
            __nv_bfloat16 vh = __float2bfloat16(v);
            hi[h] = reinterpret_cast<unsigned short&>(vh);
            lo[h] = bf16bits(v - __bfloat162float(vh));
        }
        u[r]     = (unsigned int)hi[0] | ((unsigned int)hi[1] << 16);
        u[2 + r] = (unsigned int)lo[0] | ((unsigned int)lo[1] << 16);
    }
    g_wb[idx] = make_uint4(u[0], u[1], u[2], u[3]);
}

// ---- PTX wrappers ----
__device__ __forceinline__ void ldsm4(unsigned int (&d)[4], unsigned int saddr) {
    asm volatile("ldmatrix.sync.aligned.m8n8.x4.shared.b16 {%0,%1,%2,%3}, [%4];"
                 : "=r"(d[0]), "=r"(d[1]), "=r"(d[2]), "=r"(d[3]) : "r"(saddr));
}
__device__ __forceinline__ void mma16816(float (&d)[4], const unsigned int (&a)[4],
                                         unsigned int b0, unsigned int b1) {
    asm volatile("mma.sync.aligned.m16n8k16.row.col.f32.bf16.bf16.f32 "
                 "{%0,%1,%2,%3},{%4,%5,%6,%7},{%8,%9},{%0,%1,%2,%3};"
                 : "+f"(d[0]), "+f"(d[1]), "+f"(d[2]), "+f"(d[3])
                 : "r"(a[0]), "r"(a[1]), "r"(a[2]), "r"(a[3]), "r"(b0), "r"(b1));
}

__device__ __forceinline__ float sigf(float x) {
    return __fdividef(1.0f, 1.0f + __expf(-x));
}
__device__ __forceinline__ float tanhfast(float x) {
    return 1.0f - __fdividef(2.0f, __expf(2.0f * x) + 1.0f);
}

// NOTE: every plane member explicitly 16B-aligned — ldmatrix requires 16B-aligned
// row addresses; R3 failed because fcb (8 bytes) left h0hi at offset 8 mod 16.
struct __align__(16) Smem {
    alignas(16) float4 bias0[HID];                 // (bi,bf,bg,bo) combined, layer 0
    alignas(16) float4 bias1[HID];
    alignas(16) float  fcw[2][HID];
    alignas(16) float  fcb[4];                     // [0..1] used, padded to 16B
    alignas(16) float  c0[MROWS * CP];
    alignas(16) float  c1[MROWS * CP];
    alignas(16) __nv_bfloat16 h0hi[MROWS * PH];
    alignas(16) __nv_bfloat16 h0lo[MROWS * PH];
    alignas(16) __nv_bfloat16 h1hi[MROWS * PH];
    alignas(16) __nv_bfloat16 h1lo[MROWS * PH];
    alignas(16) __nv_bfloat16 xhi[MROWS * PX];
    alignas(16) __nv_bfloat16 xlo[MROWS * PX];
};

// One k16 chunk: A from SMEM hi/lo planes (ldmatrix), B from packed GMEM frags (LDG.128),
// 3-term split-precision MMA into fp32 acc.
template <int PB>
__device__ __forceinline__ void gemm_chunk(float (&acc)[2][8][4],
                                           unsigned int shHi, unsigned int shLo,
                                           int k0, const uint4* __restrict__ wb,
                                           int mg, int ng, int lane) {
    unsigned int ah[2][4], al[2][4];
    const int rowOff = lane & 15;
    const int colB   = (k0 + ((lane >> 4) << 3)) * 2;
#pragma unroll
    for (int mt = 0; mt < 2; ++mt) {
        unsigned int off = (unsigned int)((mg * 32 + mt * 16 + rowOff) * PB + colB);
        ldsm4(ah[mt], shHi + off);
        ldsm4(al[mt], shLo + off);
    }
    const uint4* wp = wb + (ng * 8) * 32 + lane;
#pragma unroll
    for (int nt = 0; nt < 8; ++nt) {
        uint4 w = __ldg(wp + nt * 32);
#pragma unroll
        for (int mt = 0; mt < 2; ++mt) {
            mma16816(acc[mt][nt], ah[mt], w.x, w.y);   // hi*hi
            mma16816(acc[mt][nt], ah[mt], w.z, w.w);   // hi*lo
            mma16816(acc[mt][nt], al[mt], w.x, w.y);   // lo*hi
        }
    }
}

// Gate epilogue: gather (i,f,g,o) per (row,j) via lane-pair shfl, update c (SMEM fp32),
// write h as hi/lo bf16 planes.
__device__ __forceinline__ void epilogue(float (&acc)[2][8][4], const float4* __restrict__ bias4,
                                         float* __restrict__ cplane,
                                         __nv_bfloat16* __restrict__ hhi,
                                         __nv_bfloat16* __restrict__ hlo,
                                         int mg, int ng, int lane) {
    const int odd = lane & 1;
#pragma unroll
    for (int mt = 0; mt < 2; ++mt) {
        const int row = mg * 32 + mt * 16 + (lane >> 2) + (odd ? 8 : 0);
#pragma unroll
        for (int nt = 0; nt < 8; ++nt) {
            float d0 = acc[mt][nt][0], d1 = acc[mt][nt][1];
            float d2 = acc[mt][nt][2], d3 = acc[mt][nt][3];
            float e0 = __shfl_xor_sync(0xffffffffu, d0, 1);
            float e1 = __shfl_xor_sync(0xffffffffu, d1, 1);
            float e2 = __shfl_xor_sync(0xffffffffu, d2, 1);
            float e3 = __shfl_xor_sync(0xffffffffu, d3, 1);
            float gi = odd ? e2 : d0;
            float gf = odd ? e3 : d1;
            float gg = odd ? d2 : e0;
            float go = odd ? d3 : e1;
            int j = ng * 16 + nt * 2 + ((lane & 3) >> 1);
            float4 b = bias4[j];
            gi += b.x; gf += b.y; gg += b.z; go += b.w;
            float c  = cplane[row * CP + j];
            float cn = sigf(gf) * c + sigf(gi) * tanhfast(gg);
            cplane[row * CP + j] = cn;
            float h = sigf(go) * tanhfast(cn);
            __nv_bfloat16 hh = __float2bfloat16(h);
            hhi[row * PH + j] = hh;
            hlo[row * PH + j] = __float2bfloat16(h - __bfloat162float(hh));
        }
    }
}

__global__ void __launch_bounds__(NTHR, 1)
lstm_traj_kernel(const float* __restrict__ x,
                 const float* __restrict__ b_ih0, const float* __restrict__ b_hh0,
                 const float* __restrict__ b_ih1, const float* __restrict__ b_hh1,
                 const float* __restrict__ fc_w, const float* __restrict__ fc_b,
                 float* __restrict__ out) {
    extern __shared__ char smraw[];
    Smem& sm = *reinterpret_cast<Smem*>(smraw);

    const int tid  = threadIdx.x;
    const int lane = tid & 31;
    const int wid  = tid >> 5;
    const int mg   = wid >> 3;     // 0/1 -> rows [0,32)/[32,64)
    const int ng   = wid & 7;      // j range [ng*16, ng*16+16)
    const int brow0 = blockIdx.x * MROWS;

    // ---- init: zero planes, stage biases / fc ----
    for (int i = tid; i < MROWS * PH; i += NTHR) {
        sm.h0hi[i] = __float2bfloat16(0.0f); sm.h0lo[i] = __float2bfloat16(0.0f);
        sm.h1hi[i] = __float2bfloat16(0.0f); sm.h1lo[i] = __float2bfloat16(0.0f);
    }
    for (int i = tid; i < MROWS * PX; i += NTHR) {
        sm.xhi[i] = __float2bfloat16(0.0f); sm.xlo[i] = __float2bfloat16(0.0f);
    }
    for (int i = tid; i < MROWS * CP; i += NTHR) { sm.c0[i] = 0.0f; sm.c1[i] = 0.0f; }
    if (tid < HID) {
        sm.bias0[tid] = make_float4(b_ih0[tid] + b_hh0[tid],
                                    b_ih0[HID + tid] + b_hh0[HID + tid],
                                    b_ih0[2 * HID + tid] + b_hh0[2 * HID + tid],
                                    b_ih0[3 * HID + tid] + b_hh0[3 * HID + tid]);
        sm.bias1[tid] = make_float4(b_ih1[tid] + b_hh1[tid],
                                    b_ih1[HID + tid] + b_hh1[HID + tid],
                                    b_ih1[2 * HID + tid] + b_hh1[2 * HID + tid],
                                    b_ih1[3 * HID + tid] + b_hh1[3 * HID + tid]);
    }
    if (tid < 2 * HID) (&sm.fcw[0][0])[tid] = fc_w[tid];
    if (tid < 2) sm.fcb[tid] = fc_b[tid];

    const unsigned int shH0hi = (unsigned int)__cvta_generic_to_shared(sm.h0hi);
    const unsigned int shH0lo = (unsigned int)__cvta_generic_to_shared(sm.h0lo);
    const unsigned int shH1hi = (unsigned int)__cvta_generic_to_shared(sm.h1hi);
    const unsigned int shH1lo = (unsigned int)__cvta_generic_to_shared(sm.h1lo);
    const unsigned int shXhi  = (unsigned int)__cvta_generic_to_shared(sm.xhi);
    const unsigned int shXlo  = (unsigned int)__cvta_generic_to_shared(sm.xlo);

    float acc[2][8][4];

    for (int t = 0; t < SEQ + FUT; ++t) {
        // stage x_t (encoder) as bf16 hi/lo
        if (t < SEQ) {
            for (int i = tid; i < MROWS * INF; i += NTHR) {
                int r = i / INF, c = i - r * INF;
                float v = x[(size_t)(brow0 + r) * (SEQ * INF) + (size_t)t * INF + c];
                __nv_bfloat16 vh = __float2bfloat16(v);
                sm.xhi[r * PX + c] = vh;
                sm.xlo[r * PX + c] = __float2bfloat16(v - __bfloat162float(vh));
            }
        }
        __syncthreads();   // (A) x + prev-step h visible

        // ---- layer 0: [x | h0] @ W^T ----
#pragma unroll
        for (int mt = 0; mt < 2; ++mt)
#pragma unroll
            for (int nt = 0; nt < 8; ++nt)
#pragma unroll
                for (int q = 0; q < 4; ++q) acc[mt][nt][q] = 0.0f;

        gemm_chunk<PXB>(acc, shXhi, shXlo, 0, g_wb + WB_X, mg, ng, lane);
#pragma unroll 1
        for (int c = 0; c < 8; ++c)
            gemm_chunk<PHB>(acc, shH0hi, shH0lo, c * 16, g_wb + WB_H0 + c * CHK, mg, ng, lane);
        __syncthreads();   // (B) reads of old h0 done
        epilogue(acc, sm.bias0, sm.c0, sm.h0hi, sm.h0lo, mg, ng, lane);
        __syncthreads();   // (C) new h0 visible

        // ---- layer 1: [h0 | h1] @ W^T ----
#pragma unroll
        for (int mt = 0; mt < 2; ++mt)
#pragma unroll
            for (int nt = 0; nt < 8; ++nt)
#pragma unroll
                for (int q = 0; q < 4; ++q) acc[mt][nt][q] = 0.0f;

#pragma unroll 1
        for (int c = 0; c < 8; ++c)
            gemm_chunk<PHB>(acc, shH0hi, shH0lo, c * 16, g_wb + WB_I1 + c * CHK, mg, ng, lane);
#pragma unroll 1
        for (int c = 0; c < 8; ++c)
            gemm_chunk<PHB>(acc, shH1hi, shH1lo, c * 16, g_wb + WB_H1 + c * CHK, mg, ng, lane);
        __syncthreads();   // (D) reads of old h1 done
        epilogue(acc, sm.bias1, sm.c1, sm.h1hi, sm.h1lo, mg, ng, lane);

        // ---- decoder head ----
        if (t >= SEQ) {
            __syncthreads();   // (E) new h1 visible
            if (tid < 2 * MROWS) {
                int r = tid >> 1, o = tid & 1;
                float s = sm.fcb[o];
                const float* fw = &sm.fcw[o][0];
#pragma unroll 8
                for (int j = 0; j < HID; ++j) {
                    float h = __bfloat162float(sm.h1hi[r * PH + j]) +
                              __bfloat162float(sm.h1lo[r * PH + j]);
                    s += h * fw[j];
                }
                out[(size_t)(brow0 + r) * (FUT * 2) + (size_t)(t - SEQ) * 2 + o] = s;
                __nv_bfloat16 ph = __float2bfloat16(s);
                sm.xhi[r * PX + o] = ph;                               // feedback -> features 0:2
                sm.xlo[r * PX + o] = __float2bfloat16(s - __bfloat162float(ph));
            }
            // next iteration's sync (A) publishes the feedback
        }
    }
}

extern "C" void kernel_launch(void* const* d_in, const int* in_sizes, int n_in,
                              void* d_out, int out_size) {
    const float* x     = (const float*)d_in[0];
    const float* w_ih0 = (const float*)d_in[1];
    const float* w_hh0 = (const float*)d_in[2];
    const float* b_ih0 = (const float*)d_in[3];
    const float* b_hh0 = (const float*)d_in[4];
    const float* w_ih1 = (const float*)d_in[5];
    const float* w_hh1 = (const float*)d_in[6];
    const float* b_ih1 = (const float*)d_in[7];
    const float* b_hh1 = (const float*)d_in[8];
    const float* fc_w  = (const float*)d_in[9];
    const float* fc_b  = (const float*)d_in[10];
    float* out = (float*)d_out;

    pack_weights<<<(WB_TOT + 255) / 256, 256>>>(w_ih0, w_hh0, w_ih1, w_hh1);

    cudaFuncSetAttribute(lstm_traj_kernel,
                         cudaFuncAttributeMaxDynamicSharedMemorySize,
                         (int)sizeof(Smem));
    lstm_traj_kernel<<<NCTA, NTHR, sizeof(Smem)>>>(
        x, b_ih0, b_hh0, b_ih1, b_hh1, fc_w, fc_b, out);
}